// round 1
// baseline (speedup 1.0000x reference)
#include <cuda_runtime.h>
#include <math.h>

#define NN 50000
#define EE 600000
#define DD 128
#define D2 256
#define LL 7
#define BB 512
#define TT 10
#define CAP 64           // per-node cached-edge capacity (deg ~ Poisson(12))
#define BN_EPS 1e-5f
#define MSG_EPS 1e-7f

// ---------------- scratch (static device globals; no runtime alloc) ----------------
__device__ float g_h[NN * DD];          // node state
__device__ float g_r[NN * DD];          // relu(bn(h)) conv input
__device__ float g_xin[NN * DD];        // conv "out" = cin + aggr  (GEMM1 input)
__device__ float g_z[NN * D2];          // MLP hidden
__device__ float g_ea[EE * DD];         // bond embeddings, CSR(dst)-sorted
__device__ int   g_deg[NN];
__device__ int   g_rowptr[NN + 1];
__device__ int   g_cursor[NN];
__device__ int   g_eperm[EE];           // sorted-slot -> original edge id
__device__ int   g_srcs[EE];            // src node per sorted slot
__device__ float g_sum[D2], g_sumsq[D2], g_mean[D2], g_rstd[D2];
__device__ float g_pool[BB * DD];
__device__ float g_cnt[BB];

// ---------------- small utility kernels ----------------
__global__ void k_zero_deg() {
    int i = blockIdx.x * blockDim.x + threadIdx.x;
    if (i < NN) g_deg[i] = 0;
}
__global__ void k_zero_stats() {   // <<<1,256>>>
    int c = threadIdx.x;
    g_sum[c] = 0.f; g_sumsq[c] = 0.f;
}
__global__ void k_zero_pool() {
    int i = blockIdx.x * blockDim.x + threadIdx.x;
    if (i < BB * DD) g_pool[i] = 0.f;
    if (i < BB) g_cnt[i] = 0.f;
}

__global__ void k_hist(const int* __restrict__ dst) {
    int e = blockIdx.x * blockDim.x + threadIdx.x;
    if (e < EE) atomicAdd(&g_deg[dst[e]], 1);
}

// single-block exclusive scan over g_deg -> g_rowptr, g_cursor
__global__ void k_scan() {   // <<<1,1024>>>
    __shared__ int sh[1024];
    int tid = threadIdx.x;
    int carry = 0;
    for (int base = 0; base < NN; base += 1024) {
        int v = (base + tid < NN) ? g_deg[base + tid] : 0;
        sh[tid] = v;
        __syncthreads();
        for (int off = 1; off < 1024; off <<= 1) {
            int x = (tid >= off) ? sh[tid - off] : 0;
            __syncthreads();
            sh[tid] += x;
            __syncthreads();
        }
        int incl = sh[tid];
        int tot = sh[1023];
        __syncthreads();
        if (base + tid < NN) {
            int excl = carry + incl - v;
            g_rowptr[base + tid] = excl;
            g_cursor[base + tid] = excl;
        }
        carry += tot;
    }
    if (tid == 0) g_rowptr[NN] = carry;
}

__global__ void k_scatter(const int* __restrict__ src, const int* __restrict__ dst) {
    int e = blockIdx.x * blockDim.x + threadIdx.x;
    if (e < EE) {
        int p = atomicAdd(&g_cursor[dst[e]], 1);
        g_eperm[p] = e;
        g_srcs[p] = src[e];
    }
}

// ---------------- encoders ----------------
__global__ void k_atom(const int* __restrict__ x, const int* __restrict__ aoff,
                       const float* __restrict__ atab) {
    int idx = blockIdx.x * blockDim.x + threadIdx.x;
    if (idx >= NN * DD) return;
    int i = idx >> 7, d = idx & 127;
    float acc = 0.f;
#pragma unroll
    for (int f = 0; f < 9; f++) {
        int row = __ldg(&x[i * 9 + f]) + __ldg(&aoff[f]);
        acc += __ldg(&atab[row * DD + d]);
    }
    g_h[idx] = acc;
}

__global__ void k_bond(const int* __restrict__ eattr, const int* __restrict__ boff,
                       const float* __restrict__ btab) {
    int idx = blockIdx.x * blockDim.x + threadIdx.x;
    if (idx >= EE * DD) return;
    int j = idx >> 7, d = idx & 127;
    int e = __ldg(&g_eperm[j]);
    float acc = 0.f;
#pragma unroll
    for (int f = 0; f < 3; f++) {
        int row = __ldg(&eattr[e * 3 + f]) + __ldg(&boff[f]);
        acc += __ldg(&btab[row * DD + d]);
    }
    g_ea[idx] = acc;
}

// ---------------- batchnorm stats ----------------
__global__ void k_stats(const float* __restrict__ X, int C, int RPB) {  // blockDim == C
    int c = threadIdx.x;
    int r0 = blockIdx.x * RPB;
    int re = min(r0 + RPB, NN);
    float s = 0.f, s2 = 0.f;
    for (int r = r0; r < re; r++) {
        float v = X[(size_t)r * C + c];
        s += v; s2 += v * v;
    }
    atomicAdd(&g_sum[c], s);
    atomicAdd(&g_sumsq[c], s2);
}
__global__ void k_bnfin() {   // <<<1,C>>>
    int c = threadIdx.x;
    float mu = g_sum[c] / (float)NN;
    float var = g_sumsq[c] / (float)NN - mu * mu;
    g_mean[c] = mu;
    g_rstd[c] = rsqrtf(var + BN_EPS);
}

// r = relu(bn(h))
__global__ void k_prenorm(const float* __restrict__ gamma, const float* __restrict__ beta) {
    int idx = blockIdx.x * blockDim.x + threadIdx.x;
    if (idx >= NN * DD) return;
    int c = idx & 127;
    float v = g_h[idx];
    float y = (v - g_mean[c]) * g_rstd[c] * __ldg(&gamma[c]) + __ldg(&beta[c]);
    g_r[idx] = fmaxf(y, 0.f);
}

// ---------------- GENConv softmax aggregation: one block per dst node ----------------
__global__ void __launch_bounds__(128) k_aggr(const float* __restrict__ cin,
                                              const float* __restrict__ tarr, int layer) {
    __shared__ float sm[CAP * DD];
    int u = blockIdx.x, d = threadIdx.x;
    int beg = g_rowptr[u], end = g_rowptr[u + 1];
    int deg = end - beg;
    float self = cin[u * DD + d];
    if (deg == 0) { g_xin[u * DD + d] = self; return; }   // uniform per block
    float tl = __ldg(&tarr[layer]);
    float se = 0.f, sn = 0.f;
    if (deg <= CAP) {
        float mx = 0.f;
        for (int j = 0; j < deg; j++) {
            int s = __ldg(&g_srcs[beg + j]);
            float msg = fmaxf(__ldg(&cin[s * DD + d]) + __ldg(&g_ea[(size_t)(beg + j) * DD + d]), 0.f) + MSG_EPS;
            sm[j * DD + d] = msg;
            mx = fmaxf(mx, msg * tl);
        }
        for (int j = 0; j < deg; j++) {
            float msg = sm[j * DD + d];
            float e_ = expf(msg * tl - mx);
            se += e_; sn += msg * e_;
        }
    } else {   // rare fallback: recompute
        float mx = 0.f;
        for (int j = 0; j < deg; j++) {
            int s = __ldg(&g_srcs[beg + j]);
            float msg = fmaxf(__ldg(&cin[s * DD + d]) + __ldg(&g_ea[(size_t)(beg + j) * DD + d]), 0.f) + MSG_EPS;
            mx = fmaxf(mx, msg * tl);
        }
        for (int j = 0; j < deg; j++) {
            int s = __ldg(&g_srcs[beg + j]);
            float msg = fmaxf(__ldg(&cin[s * DD + d]) + __ldg(&g_ea[(size_t)(beg + j) * DD + d]), 0.f) + MSG_EPS;
            float e_ = expf(msg * tl - mx);
            se += e_; sn += msg * e_;
        }
    }
    g_xin[u * DD + d] = self + sn / (se + 1e-16f);
}

// ---------------- SIMT FP32 GEMM: C[M,NC] = op(A)[M,K] @ W[K,NC] (+bias, epilogue) ----------------
// BN_IN: A element -> relu((a-mean[k])*rstd[k]*gm[k]+bt[k]) applied at load
// ACC:   C += result (residual), else C = result
template <int K, int NC, bool BN_IN, bool ACC>
__global__ void __launch_bounds__(256, 2) k_gemm(const float* __restrict__ A,
                                                 const float* __restrict__ W,
                                                 const float* __restrict__ bias,
                                                 const float* __restrict__ gm,
                                                 const float* __restrict__ bt,
                                                 float* __restrict__ Cout) {
    constexpr int BM = 128, BN = 128, BK = 8;
    __shared__ float As[BK][BM + 4];
    __shared__ float Ws[BK][BN];
    int tid = threadIdx.x;
    int tx = tid & 15, ty = tid >> 4;
    int bm = blockIdx.y * BM, bn = blockIdx.x * BN;
    float acc[8][8];
#pragma unroll
    for (int i = 0; i < 8; i++)
#pragma unroll
        for (int j = 0; j < 8; j++) acc[i][j] = 0.f;

    const int arow = tid >> 1, akq = (tid & 1) * 4;
    const int wrow = tid >> 5, wcol = (tid & 31) << 2;

    for (int k0 = 0; k0 < K; k0 += BK) {
        float4 av = make_float4(0.f, 0.f, 0.f, 0.f);
        int gr = bm + arow;
        if (gr < NN) av = *(const float4*)(A + (size_t)gr * K + k0 + akq);
        if (BN_IN) {
            int c = k0 + akq;
            av.x = fmaxf((av.x - g_mean[c + 0]) * g_rstd[c + 0] * __ldg(&gm[c + 0]) + __ldg(&bt[c + 0]), 0.f);
            av.y = fmaxf((av.y - g_mean[c + 1]) * g_rstd[c + 1] * __ldg(&gm[c + 1]) + __ldg(&bt[c + 1]), 0.f);
            av.z = fmaxf((av.z - g_mean[c + 2]) * g_rstd[c + 2] * __ldg(&gm[c + 2]) + __ldg(&bt[c + 2]), 0.f);
            av.w = fmaxf((av.w - g_mean[c + 3]) * g_rstd[c + 3] * __ldg(&gm[c + 3]) + __ldg(&bt[c + 3]), 0.f);
        }
        As[akq + 0][arow] = av.x;
        As[akq + 1][arow] = av.y;
        As[akq + 2][arow] = av.z;
        As[akq + 3][arow] = av.w;
        *(float4*)&Ws[wrow][wcol] = *(const float4*)(W + (size_t)(k0 + wrow) * NC + bn + wcol);
        __syncthreads();
#pragma unroll
        for (int kk = 0; kk < BK; kk++) {
            float a[8], w[8];
            *(float4*)(a) = *(const float4*)&As[kk][ty * 4];
            *(float4*)(a + 4) = *(const float4*)&As[kk][64 + ty * 4];
            *(float4*)(w) = *(const float4*)&Ws[kk][tx * 4];
            *(float4*)(w + 4) = *(const float4*)&Ws[kk][64 + tx * 4];
#pragma unroll
            for (int i = 0; i < 8; i++)
#pragma unroll
                for (int j = 0; j < 8; j++) acc[i][j] += a[i] * w[j];
        }
        __syncthreads();
    }
#pragma unroll
    for (int i = 0; i < 8; i++) {
        int r = bm + ((i < 4) ? (ty * 4 + i) : (64 + ty * 4 + i - 4));
        if (r >= NN) continue;
#pragma unroll
        for (int j = 0; j < 8; j++) {
            int c = bn + ((j < 4) ? (tx * 4 + j) : (64 + tx * 4 + j - 4));
            float v = acc[i][j] + __ldg(&bias[c]);
            if (ACC) Cout[(size_t)r * NC + c] += v;
            else Cout[(size_t)r * NC + c] = v;
        }
    }
}

// ---------------- final BN + mean-pool + prediction ----------------
__global__ void k_pool(const int* __restrict__ batch, const float* __restrict__ gamma,
                       const float* __restrict__ beta) {
    int idx = blockIdx.x * blockDim.x + threadIdx.x;
    if (idx >= NN * DD) return;
    int i = idx >> 7, c = idx & 127;
    float v = g_h[idx];
    float y = (v - g_mean[c]) * g_rstd[c] * __ldg(&gamma[c]) + __ldg(&beta[c]);
    int b = __ldg(&batch[i]);
    atomicAdd(&g_pool[b * DD + c], y);
    if (c == 0) atomicAdd(&g_cnt[b], 1.f);
}

__global__ void k_pred(const float* __restrict__ pw, const float* __restrict__ pb,
                       float* __restrict__ out) {   // <<<BB,128>>>
    __shared__ float red[128];
    int b = blockIdx.x, d = threadIdx.x;
    float cnt = g_cnt[b];
    float g = g_pool[b * DD + d] / fmaxf(cnt, 1.f);
    for (int t = 0; t < TT; t++) {
        red[d] = g * __ldg(&pw[d * TT + t]);
        __syncthreads();
        for (int off = 64; off > 0; off >>= 1) {
            if (d < off) red[d] += red[d + off];
            __syncthreads();
        }
        if (d == 0) out[b * TT + t] = red[0] + __ldg(&pb[t]);
        __syncthreads();
    }
}

// ---------------- launch ----------------
extern "C" void kernel_launch(void* const* d_in, const int* in_sizes, int n_in,
                              void* d_out, int out_size) {
    (void)in_sizes; (void)n_in; (void)out_size;
    const int*   x      = (const int*)d_in[0];
    const int*   eidx   = (const int*)d_in[1];
    const int*   eattr  = (const int*)d_in[2];
    const int*   batch  = (const int*)d_in[3];
    const int*   aoff   = (const int*)d_in[4];
    const int*   boff   = (const int*)d_in[5];
    const float* atab   = (const float*)d_in[6];
    const float* btab   = (const float*)d_in[7];
    const float* ngamma = (const float*)d_in[8];
    const float* nbeta  = (const float*)d_in[9];
    const float* tarr   = (const float*)d_in[10];
    const float* w1     = (const float*)d_in[11];
    const float* b1     = (const float*)d_in[12];
    const float* bng    = (const float*)d_in[13];
    const float* bnb    = (const float*)d_in[14];
    const float* w2     = (const float*)d_in[15];
    const float* b2     = (const float*)d_in[16];
    const float* pw     = (const float*)d_in[17];
    const float* pb     = (const float*)d_in[18];
    float* out = (float*)d_out;

    const int* src = eidx;
    const int* dst = eidx + EE;

    float *p_h, *p_r, *p_xin, *p_z;
    cudaGetSymbolAddress((void**)&p_h, g_h);
    cudaGetSymbolAddress((void**)&p_r, g_r);
    cudaGetSymbolAddress((void**)&p_xin, g_xin);
    cudaGetSymbolAddress((void**)&p_z, g_z);

    // ---- build dst-sorted CSR + encoders ----
    k_zero_deg<<<(NN + 255) / 256, 256>>>();
    k_hist<<<(EE + 255) / 256, 256>>>(dst);
    k_scan<<<1, 1024>>>();
    k_scatter<<<(EE + 255) / 256, 256>>>(src, dst);
    k_atom<<<(NN * DD + 255) / 256, 256>>>(x, aoff, atab);
    k_bond<<<(EE * DD + 255) / 256, 256>>>(eattr, boff, btab);

    const dim3 g1(2, (NN + 127) / 128), g2(1, (NN + 127) / 128);

    for (int l = 0; l < LL; l++) {
        const float* cin = p_h;
        if (l > 0) {
            k_zero_stats<<<1, 256>>>();
            k_stats<<<(NN + 511) / 512, DD>>>(p_h, DD, 512);
            k_bnfin<<<1, DD>>>();
            k_prenorm<<<(NN * DD + 255) / 256, 256>>>(ngamma + l * DD, nbeta + l * DD);
            cin = p_r;
        }
        k_aggr<<<NN, 128>>>(cin, tarr, l);
        k_gemm<DD, D2, false, false><<<g1, 256>>>(p_xin, w1 + (size_t)l * DD * D2,
                                                  b1 + l * D2, nullptr, nullptr, p_z);
        k_zero_stats<<<1, 256>>>();
        k_stats<<<(NN + 511) / 512, D2>>>(p_z, D2, 512);
        k_bnfin<<<1, D2>>>();
        if (l == 0)
            k_gemm<D2, DD, true, false><<<g2, 256>>>(p_z, w2 + (size_t)l * D2 * DD,
                                                     b2 + l * DD, bng + l * D2, bnb + l * D2, p_h);
        else
            k_gemm<D2, DD, true, true><<<g2, 256>>>(p_z, w2 + (size_t)l * D2 * DD,
                                                    b2 + l * DD, bng + l * D2, bnb + l * D2, p_h);
    }

    // ---- final norm + pool + predict ----
    k_zero_stats<<<1, 256>>>();
    k_stats<<<(NN + 511) / 512, DD>>>(p_h, DD, 512);
    k_bnfin<<<1, DD>>>();
    k_zero_pool<<<(BB * DD + 255) / 256, 256>>>();
    k_pool<<<(NN * DD + 255) / 256, 256>>>(batch, ngamma, nbeta);
    k_pred<<<BB, 128>>>(pw, pb, out);
}

// round 4
// speedup vs baseline: 1.0127x; 1.0127x over previous
#include <cuda_runtime.h>
#include <math.h>

#define NN 50000
#define EE 600000
#define DD 128
#define D2 256
#define LL 7
#define BB 512
#define TT 10
#define CAP 64           // per-node cached-edge capacity (deg ~ Poisson(12))
#define BN_EPS 1e-5f
#define MSG_EPS 1e-7f

// ---------------- scratch (static device globals; no runtime alloc) ----------------
__device__ float g_h[NN * DD];          // node state
__device__ float g_r[NN * DD];          // relu(bn(h)) conv input
__device__ float g_xin[NN * DD];        // conv "out" = cin + aggr  (GEMM1 input)
__device__ float g_z[NN * D2];          // MLP hidden
__device__ float g_ea[EE * DD];         // bond embeddings, CSR(dst)-sorted
__device__ int   g_deg[NN];
__device__ int   g_rowptr[NN + 1];
__device__ int   g_cursor[NN];
__device__ int   g_eperm[EE];           // sorted-slot -> original edge id
__device__ int   g_srcs[EE];            // src node per sorted slot
__device__ float g_sum[D2], g_sumsq[D2], g_mean[D2], g_rstd[D2];
__device__ float g_pool[BB * DD];
__device__ float g_cnt[BB];

// ---------------- small utility kernels ----------------
__global__ void k_zero_deg() {
    int i = blockIdx.x * blockDim.x + threadIdx.x;
    if (i < NN) g_deg[i] = 0;
}
__global__ void k_zero_stats() {   // <<<1,256>>>
    int c = threadIdx.x;
    g_sum[c] = 0.f; g_sumsq[c] = 0.f;
}
__global__ void k_zero_pool() {
    int i = blockIdx.x * blockDim.x + threadIdx.x;
    if (i < BB * DD) g_pool[i] = 0.f;
    if (i < BB) g_cnt[i] = 0.f;
}

__global__ void k_hist(const int* __restrict__ dst) {
    int e = blockIdx.x * blockDim.x + threadIdx.x;
    if (e < EE) atomicAdd(&g_deg[dst[e]], 1);
}

// single-block exclusive scan over g_deg -> g_rowptr, g_cursor
__global__ void k_scan() {   // <<<1,1024>>>
    __shared__ int sh[1024];
    int tid = threadIdx.x;
    int carry = 0;
    for (int base = 0; base < NN; base += 1024) {
        int v = (base + tid < NN) ? g_deg[base + tid] : 0;
        sh[tid] = v;
        __syncthreads();
        for (int off = 1; off < 1024; off <<= 1) {
            int x = (tid >= off) ? sh[tid - off] : 0;
            __syncthreads();
            sh[tid] += x;
            __syncthreads();
        }
        int incl = sh[tid];
        int tot = sh[1023];
        __syncthreads();
        if (base + tid < NN) {
            int excl = carry + incl - v;
            g_rowptr[base + tid] = excl;
            g_cursor[base + tid] = excl;
        }
        carry += tot;
    }
    if (tid == 0) g_rowptr[NN] = carry;
}

__global__ void k_scatter(const int* __restrict__ src, const int* __restrict__ dst) {
    int e = blockIdx.x * blockDim.x + threadIdx.x;
    if (e < EE) {
        int p = atomicAdd(&g_cursor[dst[e]], 1);
        g_eperm[p] = e;
        g_srcs[p] = src[e];
    }
}

// ---------------- encoders ----------------
__global__ void k_atom(const int* __restrict__ x, const int* __restrict__ aoff,
                       const float* __restrict__ atab) {
    int idx = blockIdx.x * blockDim.x + threadIdx.x;
    if (idx >= NN * DD) return;
    int i = idx >> 7, d = idx & 127;
    float acc = 0.f;
#pragma unroll
    for (int f = 0; f < 9; f++) {
        int row = __ldg(&x[i * 9 + f]) + __ldg(&aoff[f]);
        acc += __ldg(&atab[row * DD + d]);
    }
    g_h[idx] = acc;
}

__global__ void k_bond(const int* __restrict__ eattr, const int* __restrict__ boff,
                       const float* __restrict__ btab) {
    int idx = blockIdx.x * blockDim.x + threadIdx.x;
    if (idx >= EE * DD) return;
    int j = idx >> 7, d = idx & 127;
    int e = __ldg(&g_eperm[j]);
    float acc = 0.f;
#pragma unroll
    for (int f = 0; f < 3; f++) {
        int row = __ldg(&eattr[e * 3 + f]) + __ldg(&boff[f]);
        acc += __ldg(&btab[row * DD + d]);
    }
    g_ea[idx] = acc;
}

// ---------------- batchnorm stats ----------------
__global__ void k_stats(const float* __restrict__ X, int C, int RPB) {  // blockDim == C
    int c = threadIdx.x;
    int r0 = blockIdx.x * RPB;
    int re = min(r0 + RPB, NN);
    float s = 0.f, s2 = 0.f;
    for (int r = r0; r < re; r++) {
        float v = X[(size_t)r * C + c];
        s += v; s2 += v * v;
    }
    atomicAdd(&g_sum[c], s);
    atomicAdd(&g_sumsq[c], s2);
}
__global__ void k_bnfin() {   // <<<1,C>>>
    int c = threadIdx.x;
    float mu = g_sum[c] / (float)NN;
    float var = g_sumsq[c] / (float)NN - mu * mu;
    g_mean[c] = mu;
    g_rstd[c] = rsqrtf(var + BN_EPS);
}

// r = relu(bn(h))
__global__ void k_prenorm(const float* __restrict__ gamma, const float* __restrict__ beta) {
    int idx = blockIdx.x * blockDim.x + threadIdx.x;
    if (idx >= NN * DD) return;
    int c = idx & 127;
    float v = g_h[idx];
    float y = (v - g_mean[c]) * g_rstd[c] * __ldg(&gamma[c]) + __ldg(&beta[c]);
    g_r[idx] = fmaxf(y, 0.f);
}

// ---------------- GENConv softmax aggregation: one block per dst node ----------------
__global__ void __launch_bounds__(128) k_aggr(const float* __restrict__ cin,
                                              const float* __restrict__ tarr, int layer) {
    __shared__ float sm[CAP * DD];
    int u = blockIdx.x, d = threadIdx.x;
    int beg = g_rowptr[u], end = g_rowptr[u + 1];
    int deg = end - beg;
    float self = cin[u * DD + d];
    if (deg == 0) { g_xin[u * DD + d] = self; return; }   // uniform per block
    float tl = __ldg(&tarr[layer]);
    float se = 0.f, sn = 0.f;
    if (deg <= CAP) {
        float mx = 0.f;
        for (int j = 0; j < deg; j++) {
            int s = __ldg(&g_srcs[beg + j]);
            float msg = fmaxf(__ldg(&cin[s * DD + d]) + __ldg(&g_ea[(size_t)(beg + j) * DD + d]), 0.f) + MSG_EPS;
            sm[j * DD + d] = msg;
            mx = fmaxf(mx, msg * tl);
        }
        for (int j = 0; j < deg; j++) {
            float msg = sm[j * DD + d];
            float e_ = expf(msg * tl - mx);
            se += e_; sn += msg * e_;
        }
    } else {   // rare fallback: recompute
        float mx = 0.f;
        for (int j = 0; j < deg; j++) {
            int s = __ldg(&g_srcs[beg + j]);
            float msg = fmaxf(__ldg(&cin[s * DD + d]) + __ldg(&g_ea[(size_t)(beg + j) * DD + d]), 0.f) + MSG_EPS;
            mx = fmaxf(mx, msg * tl);
        }
        for (int j = 0; j < deg; j++) {
            int s = __ldg(&g_srcs[beg + j]);
            float msg = fmaxf(__ldg(&cin[s * DD + d]) + __ldg(&g_ea[(size_t)(beg + j) * DD + d]), 0.f) + MSG_EPS;
            float e_ = expf(msg * tl - mx);
            se += e_; sn += msg * e_;
        }
    }
    g_xin[u * DD + d] = self + sn / (se + 1e-16f);
}

// ---------------- SIMT FP32 GEMM: C[M,NC] = op(A)[M,K] @ W[K,NC] (+bias, epilogue) ----------------
// BN_IN: A element -> relu((a-mean[k])*rstd[k]*gm[k]+bt[k]) applied at load
// ACC:   C += result (residual), else C = result
template <int K, int NC, bool BN_IN, bool ACC>
__global__ void __launch_bounds__(256, 2) k_gemm(const float* __restrict__ A,
                                                 const float* __restrict__ W,
                                                 const float* __restrict__ bias,
                                                 const float* __restrict__ gm,
                                                 const float* __restrict__ bt,
                                                 float* __restrict__ Cout) {
    constexpr int BM = 128, BN = 128, BK = 8;
    __shared__ float As[BK][BM + 4];
    __shared__ float Ws[BK][BN];
    int tid = threadIdx.x;
    int tx = tid & 15, ty = tid >> 4;
    int bm = blockIdx.y * BM, bn = blockIdx.x * BN;
    float acc[8][8];
#pragma unroll
    for (int i = 0; i < 8; i++)
#pragma unroll
        for (int j = 0; j < 8; j++) acc[i][j] = 0.f;

    const int arow = tid >> 1, akq = (tid & 1) * 4;
    const int wrow = tid >> 5, wcol = (tid & 31) << 2;

    for (int k0 = 0; k0 < K; k0 += BK) {
        float4 av = make_float4(0.f, 0.f, 0.f, 0.f);
        int gr = bm + arow;
        if (gr < NN) av = *(const float4*)(A + (size_t)gr * K + k0 + akq);
        if (BN_IN) {
            int c = k0 + akq;
            av.x = fmaxf((av.x - g_mean[c + 0]) * g_rstd[c + 0] * __ldg(&gm[c + 0]) + __ldg(&bt[c + 0]), 0.f);
            av.y = fmaxf((av.y - g_mean[c + 1]) * g_rstd[c + 1] * __ldg(&gm[c + 1]) + __ldg(&bt[c + 1]), 0.f);
            av.z = fmaxf((av.z - g_mean[c + 2]) * g_rstd[c + 2] * __ldg(&gm[c + 2]) + __ldg(&bt[c + 2]), 0.f);
            av.w = fmaxf((av.w - g_mean[c + 3]) * g_rstd[c + 3] * __ldg(&gm[c + 3]) + __ldg(&bt[c + 3]), 0.f);
        }
        As[akq + 0][arow] = av.x;
        As[akq + 1][arow] = av.y;
        As[akq + 2][arow] = av.z;
        As[akq + 3][arow] = av.w;
        *(float4*)&Ws[wrow][wcol] = *(const float4*)(W + (size_t)(k0 + wrow) * NC + bn + wcol);
        __syncthreads();
#pragma unroll
        for (int kk = 0; kk < BK; kk++) {
            float a[8], w[8];
            *(float4*)(a) = *(const float4*)&As[kk][ty * 4];
            *(float4*)(a + 4) = *(const float4*)&As[kk][64 + ty * 4];
            *(float4*)(w) = *(const float4*)&Ws[kk][tx * 4];
            *(float4*)(w + 4) = *(const float4*)&Ws[kk][64 + tx * 4];
#pragma unroll
            for (int i = 0; i < 8; i++)
#pragma unroll
                for (int j = 0; j < 8; j++) acc[i][j] += a[i] * w[j];
        }
        __syncthreads();
    }
#pragma unroll
    for (int i = 0; i < 8; i++) {
        int r = bm + ((i < 4) ? (ty * 4 + i) : (64 + ty * 4 + i - 4));
        if (r >= NN) continue;
#pragma unroll
        for (int j = 0; j < 8; j++) {
            int c = bn + ((j < 4) ? (tx * 4 + j) : (64 + tx * 4 + j - 4));
            float v = acc[i][j] + __ldg(&bias[c]);
            if (ACC) Cout[(size_t)r * NC + c] += v;
            else Cout[(size_t)r * NC + c] = v;
        }
    }
}

// ---------------- final BN + mean-pool + prediction ----------------
__global__ void k_pool(const int* __restrict__ batch, const float* __restrict__ gamma,
                       const float* __restrict__ beta) {
    int idx = blockIdx.x * blockDim.x + threadIdx.x;
    if (idx >= NN * DD) return;
    int i = idx >> 7, c = idx & 127;
    float v = g_h[idx];
    float y = (v - g_mean[c]) * g_rstd[c] * __ldg(&gamma[c]) + __ldg(&beta[c]);
    int b = __ldg(&batch[i]);
    atomicAdd(&g_pool[b * DD + c], y);
    if (c == 0) atomicAdd(&g_cnt[b], 1.f);
}

__global__ void k_pred(const float* __restrict__ pw, const float* __restrict__ pb,
                       float* __restrict__ out) {   // <<<BB,128>>>
    __shared__ float red[128];
    int b = blockIdx.x, d = threadIdx.x;
    float cnt = g_cnt[b];
    float g = g_pool[b * DD + d] / fmaxf(cnt, 1.f);
    for (int t = 0; t < TT; t++) {
        red[d] = g * __ldg(&pw[d * TT + t]);
        __syncthreads();
        for (int off = 64; off > 0; off >>= 1) {
            if (d < off) red[d] += red[d + off];
            __syncthreads();
        }
        if (d == 0) out[b * TT + t] = red[0] + __ldg(&pb[t]);
        __syncthreads();
    }
}

// ---------------- launch ----------------
extern "C" void kernel_launch(void* const* d_in, const int* in_sizes, int n_in,
                              void* d_out, int out_size) {
    (void)in_sizes; (void)n_in; (void)out_size;
    const int*   x      = (const int*)d_in[0];
    const int*   eidx   = (const int*)d_in[1];
    const int*   eattr  = (const int*)d_in[2];
    const int*   batch  = (const int*)d_in[3];
    const int*   aoff   = (const int*)d_in[4];
    const int*   boff   = (const int*)d_in[5];
    const float* atab   = (const float*)d_in[6];
    const float* btab   = (const float*)d_in[7];
    const float* ngamma = (const float*)d_in[8];
    const float* nbeta  = (const float*)d_in[9];
    const float* tarr   = (const float*)d_in[10];
    const float* w1     = (const float*)d_in[11];
    const float* b1     = (const float*)d_in[12];
    const float* bng    = (const float*)d_in[13];
    const float* bnb    = (const float*)d_in[14];
    const float* w2     = (const float*)d_in[15];
    const float* b2     = (const float*)d_in[16];
    const float* pw     = (const float*)d_in[17];
    const float* pb     = (const float*)d_in[18];
    float* out = (float*)d_out;

    const int* src = eidx;
    const int* dst = eidx + EE;

    float *p_h, *p_r, *p_xin, *p_z;
    cudaGetSymbolAddress((void**)&p_h, g_h);
    cudaGetSymbolAddress((void**)&p_r, g_r);
    cudaGetSymbolAddress((void**)&p_xin, g_xin);
    cudaGetSymbolAddress((void**)&p_z, g_z);

    // ---- build dst-sorted CSR + encoders ----
    k_zero_deg<<<(NN + 255) / 256, 256>>>();
    k_hist<<<(EE + 255) / 256, 256>>>(dst);
    k_scan<<<1, 1024>>>();
    k_scatter<<<(EE + 255) / 256, 256>>>(src, dst);
    k_atom<<<(NN * DD + 255) / 256, 256>>>(x, aoff, atab);
    k_bond<<<(EE * DD + 255) / 256, 256>>>(eattr, boff, btab);

    const dim3 g1(2, (NN + 127) / 128), g2(1, (NN + 127) / 128);

    for (int l = 0; l < LL; l++) {
        const float* cin = p_h;
        if (l > 0) {
            k_zero_stats<<<1, 256>>>();
            k_stats<<<(NN + 511) / 512, DD>>>(p_h, DD, 512);
            k_bnfin<<<1, DD>>>();
            k_prenorm<<<(NN * DD + 255) / 256, 256>>>(ngamma + l * DD, nbeta + l * DD);
            cin = p_r;
        }
        k_aggr<<<NN, 128>>>(cin, tarr, l);
        k_gemm<DD, D2, false, false><<<g1, 256>>>(p_xin, w1 + (size_t)l * DD * D2,
                                                  b1 + l * D2, nullptr, nullptr, p_z);
        k_zero_stats<<<1, 256>>>();
        k_stats<<<(NN + 511) / 512, D2>>>(p_z, D2, 512);
        k_bnfin<<<1, D2>>>();
        if (l == 0)
            k_gemm<D2, DD, true, false><<<g2, 256>>>(p_z, w2 + (size_t)l * D2 * DD,
                                                     b2 + l * DD, bng + l * D2, bnb + l * D2, p_h);
        else
            k_gemm<D2, DD, true, true><<<g2, 256>>>(p_z, w2 + (size_t)l * D2 * DD,
                                                    b2 + l * DD, bng + l * D2, bnb + l * D2, p_h);
    }

    // ---- final norm + pool + predict ----
    k_zero_stats<<<1, 256>>>();
    k_stats<<<(NN + 511) / 512, DD>>>(p_h, DD, 512);
    k_bnfin<<<1, DD>>>();
    k_zero_pool<<<(BB * DD + 255) / 256, 256>>>();
    k_pool<<<(NN * DD + 255) / 256, 256>>>(batch, ngamma, nbeta);
    k_pred<<<BB, 128>>>(pw, pb, out);
}

// round 6
// speedup vs baseline: 1.8658x; 1.8425x over previous
#include <cuda_runtime.h>
#include <cuda_bf16.h>
#include <stdint.h>
#include <math.h>

#define NN 50000
#define EE 600000
#define DD 128
#define D2 256
#define LL 7
#define BB 512
#define TT 10
#define BN_EPS 1e-5f
#define MSG_EPS 1e-7f
#define MT 391   // ceil(50000/128)

// ---------------- scratch ----------------
__device__ float g_h[NN * DD];
__device__ float g_xin[NN * DD];
__device__ float g_z[NN * D2];
__device__ float g_ea[EE * DD];
__device__ int   g_deg[NN], g_rowptr[NN + 1], g_cursor[NN], g_eperm[EE], g_srcs[EE];
__device__ float g_sum[D2], g_sumsq[D2];     // z stats
__device__ float g_hsum[DD], g_hsumsq[DD];   // h stats
__device__ float g_zsc[D2], g_zsh[D2];       // folded BN(z): y = z*sc+sh
__device__ float g_hsc[DD], g_hsh[DD];       // folded BN(h)
__device__ __nv_bfloat16 g_w1h[LL * D2 * DD], g_w1l[LL * D2 * DD];  // [l][n=256][k=128]
__device__ __nv_bfloat16 g_w2h[LL * DD * D2], g_w2l[LL * DD * D2];  // [l][n=128][k=256]
__device__ float g_pool[BB * DD];
__device__ float g_cnt[BB];

// ---------------- mma helpers (baseline PTX, no 'a'-features) ----------------
__device__ __forceinline__ uint32_t smem_u32(const void* p) {
    uint32_t a;
    asm("{ .reg .u64 t; cvta.to.shared.u64 t, %1; cvt.u32.u64 %0, t; }" : "=r"(a) : "l"(p));
    return a;
}
#define LDSM4(R, addr)                                                                      \
    asm volatile("ldmatrix.sync.aligned.m8n8.x4.shared.b16 {%0,%1,%2,%3}, [%4];"            \
        : "=r"((R)[0]), "=r"((R)[1]), "=r"((R)[2]), "=r"((R)[3]) : "r"(addr))

__device__ __forceinline__ void mma16816(float* c, const uint32_t* a, uint32_t b0, uint32_t b1) {
    asm volatile("mma.sync.aligned.m16n8k16.row.col.f32.bf16.bf16.f32 "
        "{%0,%1,%2,%3},{%4,%5,%6,%7},{%8,%9},{%0,%1,%2,%3};"
        : "+f"(c[0]), "+f"(c[1]), "+f"(c[2]), "+f"(c[3])
        : "r"(a[0]), "r"(a[1]), "r"(a[2]), "r"(a[3]), "r"(b0), "r"(b1));
}

__device__ __forceinline__ void split4(float4 v, uint2& H, uint2& Lo) {
    __nv_bfloat16 a = __float2bfloat16(v.x), b = __float2bfloat16(v.y);
    __nv_bfloat16 c = __float2bfloat16(v.z), d = __float2bfloat16(v.w);
    __nv_bfloat162 h0 = __halves2bfloat162(a, b), h1 = __halves2bfloat162(c, d);
    H.x = *(uint32_t*)&h0; H.y = *(uint32_t*)&h1;
    __nv_bfloat162 l0 = __floats2bfloat162_rn(v.x - __bfloat162float(a), v.y - __bfloat162float(b));
    __nv_bfloat162 l1 = __floats2bfloat162_rn(v.z - __bfloat162float(c), v.w - __bfloat162float(d));
    Lo.x = *(uint32_t*)&l0; Lo.y = *(uint32_t*)&l1;
}

// ---------------- utility kernels ----------------
__global__ void k_zero_deg() {
    int i = blockIdx.x * blockDim.x + threadIdx.x;
    if (i < NN) g_deg[i] = 0;
}
__global__ void k_zero_stats() {   // <<<1,256>>>
    int c = threadIdx.x;
    g_sum[c] = 0.f; g_sumsq[c] = 0.f;
}
__global__ void k_zero_pool() {
    int i = blockIdx.x * blockDim.x + threadIdx.x;
    if (i < BB * DD) g_pool[i] = 0.f;
    if (i < BB) g_cnt[i] = 0.f;
}
__global__ void k_hist(const int* __restrict__ dst) {
    int e = blockIdx.x * blockDim.x + threadIdx.x;
    if (e < EE) atomicAdd(&g_deg[dst[e]], 1);
}
__global__ void k_scan() {   // <<<1,1024>>>
    __shared__ int sh[1024];
    int tid = threadIdx.x;
    int carry = 0;
    for (int base = 0; base < NN; base += 1024) {
        int v = (base + tid < NN) ? g_deg[base + tid] : 0;
        sh[tid] = v;
        __syncthreads();
        for (int off = 1; off < 1024; off <<= 1) {
            int x = (tid >= off) ? sh[tid - off] : 0;
            __syncthreads();
            sh[tid] += x;
            __syncthreads();
        }
        int incl = sh[tid];
        int tot = sh[1023];
        __syncthreads();
        if (base + tid < NN) {
            g_rowptr[base + tid] = carry + incl - v;
            g_cursor[base + tid] = carry + incl - v;
        }
        carry += tot;
    }
    if (tid == 0) g_rowptr[NN] = carry;
}
__global__ void k_scatter(const int* __restrict__ src, const int* __restrict__ dst) {
    int e = blockIdx.x * blockDim.x + threadIdx.x;
    if (e < EE) {
        int p = atomicAdd(&g_cursor[dst[e]], 1);
        g_eperm[p] = e;
        g_srcs[p] = src[e];
    }
}
__global__ void k_atom(const int* __restrict__ x, const int* __restrict__ aoff,
                       const float* __restrict__ atab) {
    int idx = blockIdx.x * blockDim.x + threadIdx.x;
    if (idx >= NN * DD) return;
    int i = idx >> 7, d = idx & 127;
    float acc = 0.f;
#pragma unroll
    for (int f = 0; f < 9; f++) {
        int row = __ldg(&x[i * 9 + f]) + __ldg(&aoff[f]);
        acc += __ldg(&atab[row * DD + d]);
    }
    g_h[idx] = acc;
}
__global__ void k_bond(const int* __restrict__ eattr, const int* __restrict__ boff,
                       const float* __restrict__ btab) {
    int idx = blockIdx.x * blockDim.x + threadIdx.x;
    if (idx >= EE * DD) return;
    int j = idx >> 7, d = idx & 127;
    int e = __ldg(&g_eperm[j]);
    float acc = 0.f;
#pragma unroll
    for (int f = 0; f < 3; f++) {
        int row = __ldg(&eattr[e * 3 + f]) + __ldg(&boff[f]);
        acc += __ldg(&btab[row * DD + d]);
    }
    g_ea[idx] = acc;
}

// weight prep: transpose to [n][k] + bf16 split
__global__ void k_wprep1(const float* __restrict__ w1) {
    int idx = blockIdx.x * blockDim.x + threadIdx.x;
    if (idx >= LL * D2 * DD) return;
    int l = idx / (D2 * DD), rem = idx % (D2 * DD);
    int n = rem / DD, k = rem % DD;
    float v = __ldg(&w1[(size_t)l * DD * D2 + k * D2 + n]);
    __nv_bfloat16 hi = __float2bfloat16(v);
    g_w1h[idx] = hi;
    g_w1l[idx] = __float2bfloat16(v - __bfloat162float(hi));
}
__global__ void k_wprep2(const float* __restrict__ w2) {
    int idx = blockIdx.x * blockDim.x + threadIdx.x;
    if (idx >= LL * DD * D2) return;
    int l = idx / (DD * D2), rem = idx % (DD * D2);
    int n = rem / D2, k = rem % D2;
    float v = __ldg(&w2[(size_t)l * D2 * DD + k * DD + n]);
    __nv_bfloat16 hi = __float2bfloat16(v);
    g_w2h[idx] = hi;
    g_w2l[idx] = __float2bfloat16(v - __bfloat162float(hi));
}

// BN finalize (fold gamma/beta). bnfin_z also zeros h-stats; bnfin_h also zeros z-stats.
__global__ void k_bnfin_z(const float* __restrict__ bng, const float* __restrict__ bnb) { // <<<1,256>>>
    int c = threadIdx.x;
    float mu = g_sum[c] / (float)NN;
    float var = g_sumsq[c] / (float)NN - mu * mu;
    float sc = rsqrtf(var + BN_EPS) * __ldg(&bng[c]);
    g_zsc[c] = sc;
    g_zsh[c] = __ldg(&bnb[c]) - mu * sc;
    if (c < DD) { g_hsum[c] = 0.f; g_hsumsq[c] = 0.f; }
}
__global__ void k_bnfin_h(const float* __restrict__ gamma, const float* __restrict__ beta) { // <<<1,256>>>
    int c = threadIdx.x;
    if (c < DD) {
        float mu = g_hsum[c] / (float)NN;
        float var = g_hsumsq[c] / (float)NN - mu * mu;
        float sc = rsqrtf(var + BN_EPS) * __ldg(&gamma[c]);
        g_hsc[c] = sc;
        g_hsh[c] = __ldg(&beta[c]) - mu * sc;
    }
    g_sum[c] = 0.f; g_sumsq[c] = 0.f;
}

// ---------------- aggregation: online max-free softmax, BN fused ----------------
__global__ void __launch_bounds__(128) k_aggr(const float* __restrict__ tarr, int layer, int use_bn) {
    int u = blockIdx.x, d = threadIdx.x;
    float sc = use_bn ? g_hsc[d] : 1.f;
    float sh = use_bn ? g_hsh[d] : 0.f;
    float hv = g_h[u * DD + d];
    float self = use_bn ? fmaxf(fmaf(hv, sc, sh), 0.f) : hv;
    int beg = g_rowptr[u];
    int deg = g_rowptr[u + 1] - beg;
    float v = self;
    if (deg > 0) {
        float tl = __ldg(&tarr[layer]);
        float se = 0.f, sn = 0.f;
        for (int j = 0; j < deg; j++) {
            int s = __ldg(&g_srcs[beg + j]);
            float cv = __ldg(&g_h[s * DD + d]);
            if (use_bn) cv = fmaxf(fmaf(cv, sc, sh), 0.f);
            float msg = fmaxf(cv + __ldg(&g_ea[(size_t)(beg + j) * DD + d]), 0.f) + MSG_EPS;
            float e_ = __expf(msg * tl);
            se += e_;
            sn += msg * e_;
        }
        v = self + sn / (se + 1e-16f);
    }
    g_xin[u * DD + d] = v;
}

// ---------------- split-bf16 HMMA GEMM ----------------
// C[128-tile, 128-tile of NC] = op(A)[.,K] @ W[NC][K]^T ; BN_IN: A <- relu(A*zsc+zsh); ACC: C += old
// epilogue: +bias, store f32, column sum/sumsq atomics into (ssum, ssq)
template <int K, int NC, bool BN_IN, bool ACC>
__global__ void __launch_bounds__(512) k_gemm(const float* __restrict__ Ain,
                                              const __nv_bfloat16* __restrict__ Wh,
                                              const __nv_bfloat16* __restrict__ Wl,
                                              const float* __restrict__ bias,
                                              float* __restrict__ Cout,
                                              float* __restrict__ ssum, float* __restrict__ ssq) {
    // 40-half row stride: 8-row ldmatrix hits banks 20*r mod 32 -> conflict-free
    __shared__ __align__(16) uint16_t sAh[128 * 40], sAl[128 * 40];
    __shared__ __align__(16) uint16_t sBh[128 * 40], sBl[128 * 40];
    int tid = threadIdx.x, lane = tid & 31, wid = tid >> 5;
    int bm = blockIdx.x * 128, bn = blockIdx.y * 128;
    const __nv_bfloat16* WhB = Wh + (size_t)bn * K;
    const __nv_bfloat16* WlB = Wl + (size_t)bn * K;

    float acc[2][4][4];
#pragma unroll
    for (int a = 0; a < 2; a++)
#pragma unroll
        for (int b = 0; b < 4; b++)
#pragma unroll
            for (int c = 0; c < 4; c++) acc[a][b][c] = 0.f;

    const int wr = (wid & 3) * 32, wc = (wid >> 2) * 32;
    const int mrow = (lane & 7) + ((lane >> 3) & 1) * 8;   // ldmatrix row-within-16
    const int kof = (lane >> 4) * 8;                       // ldmatrix col offset

    for (int kc = 0; kc < K / 32; kc++) {
        // A: 128 rows x 32 k fp32 -> bf16 split
#pragma unroll
        for (int g = tid; g < 1024; g += 512) {
            int r = g >> 3, c4 = (g & 7) * 4;
            float4 v = make_float4(0.f, 0.f, 0.f, 0.f);
            int gr = bm + r;
            if (gr < NN) v = *(const float4*)(Ain + (size_t)gr * K + kc * 32 + c4);
            if (BN_IN) {
                int cc = kc * 32 + c4;
                v.x = fmaxf(fmaf(v.x, g_zsc[cc + 0], g_zsh[cc + 0]), 0.f);
                v.y = fmaxf(fmaf(v.y, g_zsc[cc + 1], g_zsh[cc + 1]), 0.f);
                v.z = fmaxf(fmaf(v.z, g_zsc[cc + 2], g_zsh[cc + 2]), 0.f);
                v.w = fmaxf(fmaf(v.w, g_zsc[cc + 3], g_zsh[cc + 3]), 0.f);
            }
            uint2 H, Lo;
            split4(v, H, Lo);
            *(uint2*)&sAh[r * 40 + c4] = H;
            *(uint2*)&sAl[r * 40 + c4] = Lo;
        }
        // B: 128 n x 32 k bf16 hi/lo
        {
            int r = tid >> 2, c8 = (tid & 3) * 8;
            *(uint4*)&sBh[r * 40 + c8] = *(const uint4*)(WhB + (size_t)r * K + kc * 32 + c8);
            *(uint4*)&sBl[r * 40 + c8] = *(const uint4*)(WlB + (size_t)r * K + kc * 32 + c8);
        }
        __syncthreads();

#pragma unroll
        for (int ks = 0; ks < 2; ks++) {
            uint32_t ah[2][4], al[2][4], bh[2][4], bl[2][4];
#pragma unroll
            for (int mt = 0; mt < 2; mt++) {
                uint32_t ad = smem_u32(&sAh[(wr + mt * 16 + mrow) * 40 + ks * 16 + kof]);
                LDSM4(ah[mt], ad);
                uint32_t ad2 = smem_u32(&sAl[(wr + mt * 16 + mrow) * 40 + ks * 16 + kof]);
                LDSM4(al[mt], ad2);
            }
#pragma unroll
            for (int ng = 0; ng < 2; ng++) {
                uint32_t bd = smem_u32(&sBh[(wc + ng * 16 + mrow) * 40 + ks * 16 + kof]);
                LDSM4(bh[ng], bd);
                uint32_t bd2 = smem_u32(&sBl[(wc + ng * 16 + mrow) * 40 + ks * 16 + kof]);
                LDSM4(bl[ng], bd2);
            }
#pragma unroll
            for (int mt = 0; mt < 2; mt++)
#pragma unroll
                for (int ng = 0; ng < 2; ng++)
#pragma unroll
                    for (int h = 0; h < 2; h++) {
                        float* a_ = acc[mt][ng * 2 + h];
                        mma16816(a_, ah[mt], bh[ng][h], bh[ng][h + 2]);
                        mma16816(a_, ah[mt], bl[ng][h], bl[ng][h + 2]);
                        mma16816(a_, al[mt], bh[ng][h], bh[ng][h + 2]);
                    }
        }
        __syncthreads();
    }

    // epilogue: bias (+residual), write C, column stats via shfl + atomics
    float sl[4][2], s2[4][2];
#pragma unroll
    for (int nt = 0; nt < 4; nt++) { sl[nt][0] = sl[nt][1] = s2[nt][0] = s2[nt][1] = 0.f; }
#pragma unroll
    for (int mt = 0; mt < 2; mt++) {
        int r0 = bm + wr + mt * 16 + (lane >> 2);
        int r1 = r0 + 8;
        bool v0 = r0 < NN, v1 = r1 < NN;
#pragma unroll
        for (int nt = 0; nt < 4; nt++) {
            int cg = bn + wc + nt * 8 + (lane & 3) * 2;
            float b0 = __ldg(&bias[cg]), b1 = __ldg(&bias[cg + 1]);
            float f00 = acc[mt][nt][0] + b0, f01 = acc[mt][nt][1] + b1;
            float f10 = acc[mt][nt][2] + b0, f11 = acc[mt][nt][3] + b1;
            if (v0) {
                if (ACC) {
                    float2 o = *(float2*)(Cout + (size_t)r0 * NC + cg);
                    f00 += o.x; f01 += o.y;
                }
                *(float2*)(Cout + (size_t)r0 * NC + cg) = make_float2(f00, f01);
            } else { f00 = 0.f; f01 = 0.f; }
            if (v1) {
                if (ACC) {
                    float2 o = *(float2*)(Cout + (size_t)r1 * NC + cg);
                    f10 += o.x; f11 += o.y;
                }
                *(float2*)(Cout + (size_t)r1 * NC + cg) = make_float2(f10, f11);
            } else { f10 = 0.f; f11 = 0.f; }
            sl[nt][0] += f00 + f10; sl[nt][1] += f01 + f11;
            s2[nt][0] += f00 * f00 + f10 * f10; s2[nt][1] += f01 * f01 + f11 * f11;
        }
    }
#pragma unroll
    for (int off = 4; off <= 16; off <<= 1)
#pragma unroll
        for (int nt = 0; nt < 4; nt++)
#pragma unroll
            for (int j = 0; j < 2; j++) {
                sl[nt][j] += __shfl_xor_sync(0xFFFFFFFF, sl[nt][j], off);
                s2[nt][j] += __shfl_xor_sync(0xFFFFFFFF, s2[nt][j], off);
            }
    if (lane < 4) {
#pragma unroll
        for (int nt = 0; nt < 4; nt++) {
            int cg = bn + wc + nt * 8 + lane * 2;
            atomicAdd(&ssum[cg], sl[nt][0]);
            atomicAdd(&ssum[cg + 1], sl[nt][1]);
            atomicAdd(&ssq[cg], s2[nt][0]);
            atomicAdd(&ssq[cg + 1], s2[nt][1]);
        }
    }
}

// ---------------- final pool + prediction ----------------
__global__ void k_pool(const int* __restrict__ batch) {
    int idx = blockIdx.x * blockDim.x + threadIdx.x;
    if (idx >= NN * DD) return;
    int i = idx >> 7, c = idx & 127;
    float y = fmaf(g_h[idx], g_hsc[c], g_hsh[c]);
    int b = __ldg(&batch[i]);
    atomicAdd(&g_pool[b * DD + c], y);
    if (c == 0) atomicAdd(&g_cnt[b], 1.f);
}
__global__ void k_pred(const float* __restrict__ pw, const float* __restrict__ pb,
                       float* __restrict__ out) {   // <<<BB,128>>>
    __shared__ float red[128];
    int b = blockIdx.x, d = threadIdx.x;
    float g = g_pool[b * DD + d] / fmaxf(g_cnt[b], 1.f);
    for (int t = 0; t < TT; t++) {
        red[d] = g * __ldg(&pw[d * TT + t]);
        __syncthreads();
        for (int off = 64; off > 0; off >>= 1) {
            if (d < off) red[d] += red[d + off];
            __syncthreads();
        }
        if (d == 0) out[b * TT + t] = red[0] + __ldg(&pb[t]);
        __syncthreads();
    }
}

// ---------------- launch ----------------
extern "C" void kernel_launch(void* const* d_in, const int* in_sizes, int n_in,
                              void* d_out, int out_size) {
    (void)in_sizes; (void)n_in; (void)out_size;
    const int*   x      = (const int*)d_in[0];
    const int*   eidx   = (const int*)d_in[1];
    const int*   eattr  = (const int*)d_in[2];
    const int*   batch  = (const int*)d_in[3];
    const int*   aoff   = (const int*)d_in[4];
    const int*   boff   = (const int*)d_in[5];
    const float* atab   = (const float*)d_in[6];
    const float* btab   = (const float*)d_in[7];
    const float* ngamma = (const float*)d_in[8];
    const float* nbeta  = (const float*)d_in[9];
    const float* tarr   = (const float*)d_in[10];
    const float* w1     = (const float*)d_in[11];
    const float* b1     = (const float*)d_in[12];
    const float* bng    = (const float*)d_in[13];
    const float* bnb    = (const float*)d_in[14];
    const float* w2     = (const float*)d_in[15];
    const float* b2     = (const float*)d_in[16];
    const float* pw     = (const float*)d_in[17];
    const float* pb     = (const float*)d_in[18];
    float* out = (float*)d_out;

    const int* src = eidx;
    const int* dst = eidx + EE;

    float *p_h, *p_xin, *p_z, *p_sum, *p_sumsq, *p_hsum, *p_hsumsq;
    __nv_bfloat16 *p_w1h, *p_w1l, *p_w2h, *p_w2l;
    cudaGetSymbolAddress((void**)&p_h, g_h);
    cudaGetSymbolAddress((void**)&p_xin, g_xin);
    cudaGetSymbolAddress((void**)&p_z, g_z);
    cudaGetSymbolAddress((void**)&p_sum, g_sum);
    cudaGetSymbolAddress((void**)&p_sumsq, g_sumsq);
    cudaGetSymbolAddress((void**)&p_hsum, g_hsum);
    cudaGetSymbolAddress((void**)&p_hsumsq, g_hsumsq);
    cudaGetSymbolAddress((void**)&p_w1h, g_w1h);
    cudaGetSymbolAddress((void**)&p_w1l, g_w1l);
    cudaGetSymbolAddress((void**)&p_w2h, g_w2h);
    cudaGetSymbolAddress((void**)&p_w2l, g_w2l);

    // ---- CSR build + encoders + weight prep ----
    k_zero_deg<<<(NN + 255) / 256, 256>>>();
    k_hist<<<(EE + 255) / 256, 256>>>(dst);
    k_scan<<<1, 1024>>>();
    k_scatter<<<(EE + 255) / 256, 256>>>(src, dst);
    k_atom<<<(NN * DD + 255) / 256, 256>>>(x, aoff, atab);
    k_bond<<<(EE * DD + 255) / 256, 256>>>(eattr, boff, btab);
    k_wprep1<<<(LL * D2 * DD + 255) / 256, 256>>>(w1);
    k_wprep2<<<(LL * DD * D2 + 255) / 256, 256>>>(w2);
    k_zero_stats<<<1, 256>>>();

    for (int l = 0; l < LL; l++) {
        if (l > 0)
            k_bnfin_h<<<1, 256>>>(ngamma + l * DD, nbeta + l * DD);   // also zeros z-stats
        k_aggr<<<NN, 128>>>(tarr, l, l > 0 ? 1 : 0);
        k_gemm<DD, D2, false, false><<<dim3(MT, 2), 512>>>(
            p_xin, p_w1h + (size_t)l * D2 * DD, p_w1l + (size_t)l * D2 * DD,
            b1 + l * D2, p_z, p_sum, p_sumsq);
        k_bnfin_z<<<1, 256>>>(bng + l * D2, bnb + l * D2);            // also zeros h-stats
        if (l == 0)
            k_gemm<D2, DD, true, false><<<dim3(MT, 1), 512>>>(
                p_z, p_w2h + (size_t)l * DD * D2, p_w2l + (size_t)l * DD * D2,
                b2 + l * DD, p_h, p_hsum, p_hsumsq);
        else
            k_gemm<D2, DD, true, true><<<dim3(MT, 1), 512>>>(
                p_z, p_w2h + (size_t)l * DD * D2, p_w2l + (size_t)l * DD * D2,
                b2 + l * DD, p_h, p_hsum, p_hsumsq);
    }

    // ---- final norm + pool + predict ----
    k_bnfin_h<<<1, 256>>>(ngamma, nbeta);
    k_zero_pool<<<(BB * DD + 255) / 256, 256>>>();
    k_pool<<<(NN * DD + 255) / 256, 256>>>(batch);
    k_pred<<<BB, 128>>>(pw, pb, out);
}